// round 1
// baseline (speedup 1.0000x reference)
#include <cuda_runtime.h>
#include <cuda_bf16.h>

#define BATCH   4096
#define INDIM   1024
#define OUTDIM  1024
#define NNZ     52224
#define CAP     128          // max entries per output column (mean 51, max ~80 for this data)
#define ROWS    32           // batch rows per CTA (= warp width)
#define THREADS 512          // 16 warps, 64 output columns per warp
#define SSTRIDE 33           // padded smem stride: bank-conflict-free transpose + gather

// Device scratch (allocation-free rule: __device__ globals)
__device__ int g_len[OUTDIM];
__device__ int g_len4[OUTDIM];
__device__ __align__(16) int   g_ii[OUTDIM * CAP];
__device__ __align__(16) float g_w [OUTDIM * CAP];

// ---------------- preprocessing: bucket NNZ by output column ----------------

__global__ void k_zero() {
    int j = blockIdx.x * blockDim.x + threadIdx.x;
    if (j < OUTDIM) g_len[j] = 0;
}

__global__ void k_fill(const int* __restrict__ ind_in,
                       const int* __restrict__ ind_out,
                       const float* __restrict__ weight) {
    int k = blockIdx.x * blockDim.x + threadIdx.x;
    if (k < NNZ) {
        int j = ind_out[k];
        int p = atomicAdd(&g_len[j], 1);
        if (p < CAP) {
            g_ii[j * CAP + p] = ind_in[k];
            g_w [j * CAP + p] = weight[k];
        }
    }
}

__global__ void k_pad() {
    int j = blockIdx.x * blockDim.x + threadIdx.x;
    if (j < OUTDIM) {
        int n  = min(g_len[j], CAP);
        int n4 = (n + 3) & ~3;                    // pad to multiple of 4 for LDG.128
        for (int p = n; p < n4; ++p) {
            g_ii[j * CAP + p] = 0;
            g_w [j * CAP + p] = 0.0f;
        }
        g_len4[j] = n4;
    }
}

// ---------------- main kernel: per-column register accumulation ----------------
//
// CTA = 32 batch rows. Input tile transposed into smem: in_s[col*33 + row].
// Warp processes 64 output columns; lane <-> batch row. For each column j,
// all lanes walk j's entry list together (broadcast LDG.128), gather from
// smem conflict-free (bank = (ii + lane) % 32, distinct per lane), and
// accumulate in registers. No atomics anywhere.

__global__ __launch_bounds__(THREADS, 1)
void k_main(const float* __restrict__ input,
            const float* __restrict__ bias,
            float* __restrict__ out) {
    extern __shared__ float in_s[];               // [INDIM][SSTRIDE] floats
    const int tid      = threadIdx.x;
    const int base_row = blockIdx.x * ROWS;

    // Stage transposed input tile (coalesced global reads, conflict-free STS)
    for (int idx = tid; idx < ROWS * INDIM; idx += THREADS) {
        int row = idx >> 10;                      // / INDIM
        int col = idx & (INDIM - 1);
        in_s[col * SSTRIDE + row] = input[(size_t)(base_row + row) * INDIM + col];
    }
    __syncthreads();

    const int warp = tid >> 5;
    const int lane = tid & 31;
    const int cols_per_warp = OUTDIM / (THREADS / 32);   // 64
    const int jwarp = warp * cols_per_warp;
    float* orow = out + (size_t)(base_row + lane) * OUTDIM;

    for (int g = 0; g < cols_per_warp / 32; ++g) {
        float acc[32];
        #pragma unroll
        for (int c = 0; c < 32; ++c) {
            const int j  = jwarp + g * 32 + c;
            const int n4 = g_len4[j] >> 2;
            const int4*   iip = (const int4*  )(g_ii + j * CAP);
            const float4* wp  = (const float4*)(g_w  + j * CAP);
            float a0 = 0.0f, a1 = 0.0f;
            for (int p = 0; p < n4; ++p) {
                int4   ii = iip[p];
                float4 w  = wp[p];
                a0 += in_s[ii.x * SSTRIDE + lane] * w.x;
                a1 += in_s[ii.y * SSTRIDE + lane] * w.y;
                a0 += in_s[ii.z * SSTRIDE + lane] * w.z;
                a1 += in_s[ii.w * SSTRIDE + lane] * w.w;
            }
            acc[c] = a0 + a1 + bias[j];
        }
        // Vectorized output: each lane writes its row's 32-column chunk as 8x float4
        float* op = orow + jwarp + g * 32;
        #pragma unroll
        for (int q = 0; q < 8; ++q) {
            *(float4*)(op + q * 4) =
                make_float4(acc[q * 4], acc[q * 4 + 1], acc[q * 4 + 2], acc[q * 4 + 3]);
        }
    }
}

// ---------------- launch ----------------

extern "C" void kernel_launch(void* const* d_in, const int* in_sizes, int n_in,
                              void* d_out, int out_size) {
    const float* input   = (const float*)d_in[0];   // [4096,1024] f32
    const float* weight  = (const float*)d_in[1];   // [52224]     f32
    const float* bias    = (const float*)d_in[2];   // [1024]      f32
    const int*   ind_in  = (const int*)  d_in[3];   // [52224]     i32
    const int*   ind_out = (const int*)  d_in[4];   // [52224]     i32
    float*       out     = (float*)d_out;           // [4096,1024] f32

    const int smem_bytes = INDIM * SSTRIDE * (int)sizeof(float);  // 135168
    cudaFuncSetAttribute(k_main, cudaFuncAttributeMaxDynamicSharedMemorySize, smem_bytes);

    k_zero<<<(OUTDIM + 255) / 256, 256>>>();
    k_fill<<<(NNZ + 255) / 256, 256>>>(ind_in, ind_out, weight);
    k_pad <<<(OUTDIM + 255) / 256, 256>>>();
    k_main<<<BATCH / ROWS, THREADS, smem_bytes>>>(input, bias, out);
}

// round 2
// speedup vs baseline: 1.1345x; 1.1345x over previous
#include <cuda_runtime.h>
#include <cuda_bf16.h>

#define BATCH   4096
#define INDIM   1024
#define OUTDIM  1024
#define NNZ     52224
#define CAP     128          // max entries per output column (mean ~51)
#define ROWS    32           // batch rows per CTA (= warp width)
#define THREADS 1024         // 32 warps, 32 output columns per warp
#define CPW     32           // cols per warp
#define HALF    16           // cols per register batch
#define SSTRIDE 33           // padded smem stride (floats): conflict-free fill + gather

// Device scratch (allocation-free rule: __device__ globals)
__device__ int g_len[OUTDIM];
__device__ int g_len4[OUTDIM];
__device__ __align__(16) int   g_ii[OUTDIM * CAP];   // stores BYTE offsets: ind_in*SSTRIDE*4
__device__ __align__(16) float g_w [OUTDIM * CAP];

// ---------------- preprocessing: bucket NNZ by output column ----------------

__global__ void k_zero() {
    int j = blockIdx.x * blockDim.x + threadIdx.x;
    if (j < OUTDIM) g_len[j] = 0;
}

__global__ void k_fill(const int* __restrict__ ind_in,
                       const int* __restrict__ ind_out,
                       const float* __restrict__ weight) {
    int k = blockIdx.x * blockDim.x + threadIdx.x;
    if (k < NNZ) {
        int j = ind_out[k];
        int p = atomicAdd(&g_len[j], 1);
        if (p < CAP) {
            g_ii[j * CAP + p] = ind_in[k] * (SSTRIDE * 4);   // precomputed byte offset
            g_w [j * CAP + p] = weight[k];
        }
    }
}

__global__ void k_pad() {
    int j = blockIdx.x * blockDim.x + threadIdx.x;
    if (j < OUTDIM) {
        int n  = min(g_len[j], CAP);
        int n4 = (n + 3) & ~3;                    // pad to multiple of 4 for LDG.128
        for (int p = n; p < n4; ++p) {
            g_ii[j * CAP + p] = 0;
            g_w [j * CAP + p] = 0.0f;
        }
        g_len4[j] = n4;
    }
}

// ---------------- main kernel: per-column register accumulation ----------------
//
// CTA = 32 batch rows, 32 warps. Input tile transposed into smem:
// in_s[col*SSTRIDE + row]. Warp owns 32 output columns (two batches of 16);
// lane <-> batch row. Per entry: broadcast LDG.128 of (ii,w), one IADD for the
// smem address (byte offsets precomputed), one conflict-free LDS, one FFMA.
// No atomics anywhere.

__global__ __launch_bounds__(THREADS, 1)
void k_main(const float* __restrict__ input,
            const float* __restrict__ bias,
            float* __restrict__ out) {
    extern __shared__ float in_s[];               // [INDIM][SSTRIDE] floats
    const int tid      = threadIdx.x;
    const int base_row = blockIdx.x * ROWS;

    // Stage transposed input tile (coalesced global reads, conflict-free STS)
    for (int idx = tid; idx < ROWS * INDIM; idx += THREADS) {
        int row = idx >> 10;                      // / INDIM
        int col = idx & (INDIM - 1);
        in_s[col * SSTRIDE + row] = input[(size_t)(base_row + row) * INDIM + col];
    }
    __syncthreads();

    const int warp = tid >> 5;
    const int lane = tid & 31;
    const char* lane_base = (const char*)in_s + lane * 4;
    const int jwarp = warp * CPW;
    float* orow = out + (size_t)(base_row + lane) * OUTDIM;

    #pragma unroll
    for (int g = 0; g < CPW / HALF; ++g) {
        float acc[HALF];
        #pragma unroll
        for (int c = 0; c < HALF; ++c) {
            const int j  = jwarp + g * HALF + c;
            const int n4 = g_len4[j] >> 2;
            const int4*   iip = (const int4*  )(g_ii + j * CAP);
            const float4* wp  = (const float4*)(g_w  + j * CAP);
            float a0 = 0.0f, a1 = 0.0f;
            for (int p = 0; p < n4; ++p) {
                int4   ii = iip[p];
                float4 w  = wp[p];
                a0 += *(const float*)(lane_base + ii.x) * w.x;
                a1 += *(const float*)(lane_base + ii.y) * w.y;
                a0 += *(const float*)(lane_base + ii.z) * w.z;
                a1 += *(const float*)(lane_base + ii.w) * w.w;
            }
            acc[c] = a0 + a1 + bias[j];
        }
        // Vectorized output: each lane writes its row's 16-column chunk as 4x float4
        float* op = orow + jwarp + g * HALF;
        #pragma unroll
        for (int q = 0; q < HALF / 4; ++q) {
            *(float4*)(op + q * 4) =
                make_float4(acc[q * 4], acc[q * 4 + 1], acc[q * 4 + 2], acc[q * 4 + 3]);
        }
    }
}

// ---------------- launch ----------------

extern "C" void kernel_launch(void* const* d_in, const int* in_sizes, int n_in,
                              void* d_out, int out_size) {
    const float* input   = (const float*)d_in[0];   // [4096,1024] f32
    const float* weight  = (const float*)d_in[1];   // [52224]     f32
    const float* bias    = (const float*)d_in[2];   // [1024]      f32
    const int*   ind_in  = (const int*)  d_in[3];   // [52224]     i32
    const int*   ind_out = (const int*)  d_in[4];   // [52224]     i32
    float*       out     = (float*)d_out;           // [4096,1024] f32

    const int smem_bytes = INDIM * SSTRIDE * (int)sizeof(float);  // 135168
    cudaFuncSetAttribute(k_main, cudaFuncAttributeMaxDynamicSharedMemorySize, smem_bytes);

    k_zero<<<(OUTDIM + 255) / 256, 256>>>();
    k_fill<<<(NNZ + 255) / 256, 256>>>(ind_in, ind_out, weight);
    k_pad <<<(OUTDIM + 255) / 256, 256>>>();
    k_main<<<BATCH / ROWS, THREADS, smem_bytes>>>(input, bias, out);
}